// round 5
// baseline (speedup 1.0000x reference)
#include <cuda_runtime.h>
#include <cstdint>

// ---------------------------------------------------------------------------
// QuantizedLinear: y[t,o] = scale[o] * sum_k x[t,k]*qW[o,k] + bias[o]
// TOKENS=256, IN_F=4096, OUT_F=14336. qW int32 in [0,127) -> exact in tf32.
//
// NOTE: harness compiles to PTX target compute_100 (no 'a') -> tcgen05 is
// unavailable. Use portable mma.sync m16n8k8 tf32 + cp.async instead.
// ---------------------------------------------------------------------------

#define TOKENS 256
#define IN_F   4096
#define OUT_F  14336

#define M_TILE 128        // tokens per CTA
#define N_TILE 256        // out features per CTA
#define KC     16         // K per pipeline stage
#define NST    (IN_F / KC)   // 256 stages
#define S      4          // pipeline depth
#define NTHREADS 256

// SMEM rows padded to 20 floats (80B): makes the m16n8k8 fragment LDS pattern
// bank-conflict-free (bank = (20*(t/4) + t%4) mod 32 -> all 32 distinct).
#define ROWF   20
#define ROWB   (ROWF * 4)           // 80 bytes
#define A_STAGE_B (M_TILE * ROWB)   // 10240
#define B_STAGE_B (N_TILE * ROWB)   // 20480

// SMEM layout (dynamic): scale[256] | bias[256] | A stages | B stages
#define SM_SCALE 0
#define SM_BIAS  1024
#define SM_A0    2048
#define SM_B0    (SM_A0 + S * A_STAGE_B)            // 43008
#define SM_TOTAL (SM_B0 + S * B_STAGE_B)            // 124928

// 4MB scratch: x rounded to tf32 (f32 bit patterns)
__device__ uint32_t g_x_tf32[TOKENS * IN_F];

// ---------------------------------------------------------------------------
__device__ __forceinline__ uint32_t smem_u32(const void* p) {
    uint32_t a;
    asm("{ .reg .u64 t; cvta.to.shared.u64 t, %1; cvt.u32.u64 %0, t; }"
        : "=r"(a) : "l"(p));
    return a;
}

#define CP_ASYNC16(dst, src) \
    asm volatile("cp.async.cg.shared.global [%0], [%1], 16;" :: "r"(dst), "l"(src))
#define CP_COMMIT() asm volatile("cp.async.commit_group;" ::: "memory")
#define CP_WAIT(n)  asm volatile("cp.async.wait_group %0;" :: "n"(n) : "memory")

__device__ __forceinline__ void mma_tf32(float* c, const uint32_t* a, const uint32_t* b) {
    asm volatile(
        "mma.sync.aligned.m16n8k8.row.col.f32.tf32.tf32.f32 "
        "{%0,%1,%2,%3}, {%4,%5,%6,%7}, {%8,%9}, {%0,%1,%2,%3};"
        : "+f"(c[0]), "+f"(c[1]), "+f"(c[2]), "+f"(c[3])
        : "r"(a[0]), "r"(a[1]), "r"(a[2]), "r"(a[3]), "r"(b[0]), "r"(b[1]));
}

__device__ __forceinline__ uint32_t lds_u32(uint32_t addr) {
    uint32_t v;
    asm volatile("ld.shared.b32 %0, [%1];" : "=r"(v) : "r"(addr));
    return v;
}

// ---------------------------------------------------------------------------
// Kernel 1: round x to tf32 (round-to-nearest) into scratch
// ---------------------------------------------------------------------------
__global__ void __launch_bounds__(256) prep_x_kernel(const float* __restrict__ x) {
    int i = blockIdx.x * blockDim.x + threadIdx.x;
    if (i < TOKENS * IN_F) {
        uint32_t r;
        asm("cvt.rna.tf32.f32 %0, %1;" : "=r"(r) : "f"(x[i]));
        g_x_tf32[i] = r;
    }
}

// ---------------------------------------------------------------------------
// Kernel 2: tf32 mma.sync GEMM, cp.async 4-stage pipeline, inline W convert
// ---------------------------------------------------------------------------
__global__ void __launch_bounds__(NTHREADS, 1) qlin_gemm_kernel(
    const int*   __restrict__ W,      // [OUT_F, IN_F] int32
    const float* __restrict__ scale,  // [OUT_F]
    const float* __restrict__ bias,   // [OUT_F]
    float*       __restrict__ out)    // [TOKENS, OUT_F]
{
    extern __shared__ char smem[];
    const uint32_t sb = smem_u32(smem);
    const int tid = threadIdx.x;
    const int wid = tid >> 5;
    const int lid = tid & 31;
    const int qt  = lid >> 2;   // 0..7
    const int rt  = lid & 3;    // 0..3
    const int wm  = wid & 1;    // 2 M warp-groups (64 rows each)
    const int wn  = wid >> 1;   // 4 N warp-groups (64 cols each)
    const int n0  = blockIdx.x * N_TILE;
    const int m0  = blockIdx.y * M_TILE;

    // stage scale/bias for this N tile
    ((float*)(smem + SM_SCALE))[tid] = scale[n0 + tid];
    ((float*)(smem + SM_BIAS))[tid]  = bias[n0 + tid];

    // ---- per-thread cp.async chunk mapping (16B chunks) -------------------
    // A stage: 128 rows x 64B data = 512 chunks -> 2/thread
    // B stage: 256 rows x 64B data = 1024 chunks -> 4/thread
    uint32_t aSoff[2]; const uint32_t* aG[2];
    uint32_t bSoff[4]; const int*      bG[4];
#pragma unroll
    for (int i = 0; i < 2; i++) {
        int c = tid + i * NTHREADS;          // 0..511
        int row = c >> 2, k16 = c & 3;
        aSoff[i] = (uint32_t)(row * ROWB + k16 * 16);
        aG[i]    = g_x_tf32 + (size_t)(m0 + row) * IN_F + k16 * 4;
    }
#pragma unroll
    for (int i = 0; i < 4; i++) {
        int c = tid + i * NTHREADS;          // 0..1023
        int row = c >> 2, k16 = c & 3;
        bSoff[i] = (uint32_t)(row * ROWB + k16 * 16);
        bG[i]    = W + (size_t)(n0 + row) * IN_F + k16 * 4;
    }

    // ---- prologue: prefetch stages 0..S-2 ---------------------------------
#pragma unroll
    for (int s = 0; s < S - 1; s++) {
        const uint32_t ab = sb + SM_A0 + s * A_STAGE_B;
        const uint32_t bb = sb + SM_B0 + s * B_STAGE_B;
        const int kb = s * KC;
#pragma unroll
        for (int i = 0; i < 2; i++) CP_ASYNC16(ab + aSoff[i], aG[i] + kb);
#pragma unroll
        for (int i = 0; i < 4; i++) CP_ASYNC16(bb + bSoff[i], bG[i] + kb);
        CP_COMMIT();
    }

    // accumulators: 4 m-tiles x 8 n-tiles x 4 regs
    float acc[4][8][4];
#pragma unroll
    for (int i = 0; i < 4; i++)
#pragma unroll
        for (int j = 0; j < 8; j++)
#pragma unroll
            for (int c = 0; c < 4; c++) acc[i][j][c] = 0.0f;

    // per-warp SMEM bases for fragment loads (stage offset added per iter)
    const uint32_t aWbase = sb + SM_A0 + (uint32_t)((wm * 64 + qt) * ROWB + rt * 4);
    const uint32_t bWbase = sb + SM_B0 + (uint32_t)((wn * 64 + qt) * ROWB + rt * 4);

    // ---- main loop --------------------------------------------------------
#pragma unroll 1
    for (int s = 0; s < NST; s++) {
        const int buf = s & (S - 1);

        if (s + S - 1 < NST) { CP_WAIT(S - 2); } else { CP_WAIT(0); }

        // convert own W chunks int32 -> f32 in place (exact for 0..126)
        {
            char* bbuf = smem + SM_B0 + buf * B_STAGE_B;
#pragma unroll
            for (int i = 0; i < 4; i++) {
                int4 v = *reinterpret_cast<const int4*>(bbuf + bSoff[i]);
                float4 f;
                f.x = __int2float_rn(v.x);
                f.y = __int2float_rn(v.y);
                f.z = __int2float_rn(v.z);
                f.w = __int2float_rn(v.w);
                *reinterpret_cast<float4*>(bbuf + bSoff[i]) = f;
            }
        }
        __syncthreads();   // conversion visible; stage s-1 reads all retired

        // prefetch stage s+S-1 into the buffer freed at iteration s-1
        if (s + S - 1 < NST) {
            const int ps = s + S - 1;
            const int pb = ps & (S - 1);
            const uint32_t ab = sb + SM_A0 + pb * A_STAGE_B;
            const uint32_t bb = sb + SM_B0 + pb * B_STAGE_B;
            const int kb = ps * KC;
#pragma unroll
            for (int i = 0; i < 2; i++) CP_ASYNC16(ab + aSoff[i], aG[i] + kb);
#pragma unroll
            for (int i = 0; i < 4; i++) CP_ASYNC16(bb + bSoff[i], bG[i] + kb);
            CP_COMMIT();
        }

        // compute stage s: KC=16 -> two k8 steps
        const uint32_t aS = aWbase + buf * A_STAGE_B;
        const uint32_t bS = bWbase + buf * B_STAGE_B;
#pragma unroll
        for (int kk = 0; kk < 2; kk++) {
            const uint32_t ko = (uint32_t)(kk * 8 * 4);
            uint32_t a[4][4], b[8][2];
#pragma unroll
            for (int i = 0; i < 4; i++) {
                const uint32_t base = aS + (uint32_t)(i * 16 * ROWB) + ko;
                a[i][0] = lds_u32(base);
                a[i][1] = lds_u32(base + 8 * ROWB);
                a[i][2] = lds_u32(base + 16);
                a[i][3] = lds_u32(base + 8 * ROWB + 16);
            }
#pragma unroll
            for (int j = 0; j < 8; j++) {
                const uint32_t base = bS + (uint32_t)(j * 8 * ROWB) + ko;
                b[j][0] = lds_u32(base);
                b[j][1] = lds_u32(base + 16);
            }
#pragma unroll
            for (int i = 0; i < 4; i++)
#pragma unroll
                for (int j = 0; j < 8; j++)
                    mma_tf32(acc[i][j], a[i], b[j]);
        }
        // no trailing barrier: next iteration's __syncthreads covers reuse
    }

    // ---- epilogue ---------------------------------------------------------
    const float* s_sc = (const float*)(smem + SM_SCALE);
    const float* s_bi = (const float*)(smem + SM_BIAS);
#pragma unroll
    for (int i = 0; i < 4; i++) {
        const int m = m0 + wm * 64 + i * 16 + qt;
#pragma unroll
        for (int j = 0; j < 8; j++) {
            const int nl = wn * 64 + j * 8 + 2 * rt;   // local n of c0
            const float sc0 = s_sc[nl],     bi0 = s_bi[nl];
            const float sc1 = s_sc[nl + 1], bi1 = s_bi[nl + 1];
            float2 v0 = { acc[i][j][0] * sc0 + bi0, acc[i][j][1] * sc1 + bi1 };
            float2 v1 = { acc[i][j][2] * sc0 + bi0, acc[i][j][3] * sc1 + bi1 };
            *reinterpret_cast<float2*>(out + (size_t)m * OUT_F + n0 + nl) = v0;
            *reinterpret_cast<float2*>(out + (size_t)(m + 8) * OUT_F + n0 + nl) = v1;
        }
    }
}

// ---------------------------------------------------------------------------
extern "C" void kernel_launch(void* const* d_in, const int* in_sizes, int n_in,
                              void* d_out, int out_size) {
    const float* x     = (const float*)d_in[0];
    const int*   W     = (const int*)  d_in[1];
    const float* scale = (const float*)d_in[2];
    const float* bias  = (const float*)d_in[3];
    float*       out   = (float*)d_out;

    (void)in_sizes; (void)n_in; (void)out_size;

    cudaFuncSetAttribute(qlin_gemm_kernel,
                         cudaFuncAttributeMaxDynamicSharedMemorySize, SM_TOTAL);

    prep_x_kernel<<<(TOKENS * IN_F + 255) / 256, 256>>>(x);

    dim3 grid(OUT_F / N_TILE, TOKENS / M_TILE);   // (56, 2)
    qlin_gemm_kernel<<<grid, NTHREADS, SM_TOTAL>>>(W, scale, bias, out);
}

// round 6
// speedup vs baseline: 1.9415x; 1.9415x over previous
#include <cuda_runtime.h>
#include <cuda_fp16.h>
#include <cstdint>

// ---------------------------------------------------------------------------
// QuantizedLinear: y[t,o] = scale[o] * sum_k x[t,k]*qW[o,k] + bias[o]
// TOKENS=256, IN_F=4096, OUT_F=14336. qW int32 in [0,127) -> exact in fp16.
// fp16 mma.sync m16n8k16 (f32 accum), cp.async 3-stage pipeline, 2 CTAs/SM.
// x pre-rounded to fp16; W converted int32->fp16 in SMEM per stage.
// ---------------------------------------------------------------------------

#define TOKENS 256
#define IN_F   4096
#define OUT_F  14336

#define M_TILE 128
#define N_TILE 128
#define KC     32                 // K elems per stage
#define NST    (IN_F / KC)        // 128 stages
#define S      3                  // cp.async pipeline depth
#define NTHREADS 256

// fp16 tile rows: 32 halfs = 64B data + 16B pad = 80B (bank stride 20:
// banks (20*g + t) mod 32 are all-distinct for g=0..7, t=0..3 -> conflict-free)
#define ROWB      80
#define A_STAGE_B (M_TILE * ROWB)     // 10240
#define BI_STAGE_B (N_TILE * 128)     // 16384 (int32 staging rows: 32*4B)
#define BF_BUF_B  (N_TILE * ROWB)     // 10240

#define SM_SCALE 0
#define SM_BIAS  512
#define SM_A0    1024
#define SM_BI0   (SM_A0 + S * A_STAGE_B)     // 31744
#define SM_BF0   (SM_BI0 + S * BI_STAGE_B)   // 80896
#define SM_TOTAL (SM_BF0 + 2 * BF_BUF_B)     // 101376  (x2 CTAs = 202752 < 227KB)

// 2MB scratch: x rounded to fp16
__device__ __half g_x_f16[TOKENS * IN_F];

// ---------------------------------------------------------------------------
__device__ __forceinline__ uint32_t smem_u32(const void* p) {
    uint32_t a;
    asm("{ .reg .u64 t; cvta.to.shared.u64 t, %1; cvt.u32.u64 %0, t; }"
        : "=r"(a) : "l"(p));
    return a;
}

#define CP_ASYNC16(dst, src) \
    asm volatile("cp.async.cg.shared.global [%0], [%1], 16;" :: "r"(dst), "l"(src))
#define CP_COMMIT() asm volatile("cp.async.commit_group;" ::: "memory")
#define CP_WAIT(n)  asm volatile("cp.async.wait_group %0;" :: "n"(n) : "memory")

__device__ __forceinline__ void mma_f16(float* c, const uint32_t* a, const uint32_t* b) {
    asm volatile(
        "mma.sync.aligned.m16n8k16.row.col.f32.f16.f16.f32 "
        "{%0,%1,%2,%3}, {%4,%5,%6,%7}, {%8,%9}, {%0,%1,%2,%3};"
        : "+f"(c[0]), "+f"(c[1]), "+f"(c[2]), "+f"(c[3])
        : "r"(a[0]), "r"(a[1]), "r"(a[2]), "r"(a[3]), "r"(b[0]), "r"(b[1]));
}

__device__ __forceinline__ uint32_t lds_u32(uint32_t addr) {
    uint32_t v;
    asm volatile("ld.shared.b32 %0, [%1];" : "=r"(v) : "r"(addr));
    return v;
}

// ---------------------------------------------------------------------------
// Kernel 1: round x to fp16 into scratch
// ---------------------------------------------------------------------------
__global__ void __launch_bounds__(256) prep_x_kernel(const float* __restrict__ x) {
    int i = blockIdx.x * blockDim.x + threadIdx.x;
    if (i < TOKENS * IN_F) g_x_f16[i] = __float2half_rn(x[i]);
}

// ---------------------------------------------------------------------------
// Kernel 2: fp16 mma.sync GEMM, 3-stage cp.async, inline int32->fp16 convert
// ---------------------------------------------------------------------------
__global__ void __launch_bounds__(NTHREADS, 2) qlin_gemm_kernel(
    const int*   __restrict__ W,      // [OUT_F, IN_F] int32
    const float* __restrict__ scale,  // [OUT_F]
    const float* __restrict__ bias,   // [OUT_F]
    float*       __restrict__ out)    // [TOKENS, OUT_F]
{
    extern __shared__ char smem[];
    const uint32_t sb = smem_u32(smem);
    const int tid = threadIdx.x;
    const int wid = tid >> 5;
    const int lid = tid & 31;
    const int g   = lid >> 2;    // 0..7
    const int t   = lid & 3;     // 0..3
    const int wm  = wid & 1;     // 2 M warp-rows (64 tokens each)
    const int wn  = wid >> 1;    // 4 N warp-cols (32 feats each)
    const int n0  = blockIdx.x * N_TILE;
    const int m0  = blockIdx.y * M_TILE;

    if (tid < N_TILE) {
        ((float*)(smem + SM_SCALE))[tid] = scale[n0 + tid];
        ((float*)(smem + SM_BIAS))[tid]  = bias[n0 + tid];
    }

    // ---- per-thread cp.async chunk mapping --------------------------------
    // A stage: 128 rows x 64B = 512 x16B chunks -> 2/thread
    uint32_t aSoff[2]; const __half* aG[2];
#pragma unroll
    for (int i = 0; i < 2; i++) {
        int c = tid + i * NTHREADS;         // 0..511
        int row = c >> 2, ca = c & 3;
        aSoff[i] = (uint32_t)(row * ROWB + ca * 16);
        aG[i]    = g_x_f16 + (size_t)(m0 + row) * IN_F + ca * 8;   // 8 halfs/16B
    }
    // B int stage: 128 rows x 128B = 1024 x16B chunks -> 4/thread
    uint32_t bIoff[4], bFoff[4]; const int* bG[4];
#pragma unroll
    for (int i = 0; i < 4; i++) {
        int c = tid + i * NTHREADS;         // 0..1023
        int row = c >> 3, cb = c & 7;
        bIoff[i] = (uint32_t)(row * 128 + cb * 16);
        bFoff[i] = (uint32_t)(row * ROWB + cb * 8);
        bG[i]    = W + (size_t)(n0 + row) * IN_F + cb * 4;         // 4 ints/16B
    }

    // ---- prologue: prefetch stages 0..S-2 ---------------------------------
#pragma unroll
    for (int s = 0; s < S - 1; s++) {
        const uint32_t ab = sb + SM_A0  + s * A_STAGE_B;
        const uint32_t bb = sb + SM_BI0 + s * BI_STAGE_B;
        const int kb = s * KC;
#pragma unroll
        for (int i = 0; i < 2; i++) CP_ASYNC16(ab + aSoff[i], aG[i] + kb);
#pragma unroll
        for (int i = 0; i < 4; i++) CP_ASYNC16(bb + bIoff[i], bG[i] + kb);
        CP_COMMIT();
    }

    // accumulators: 4 m-tiles (16) x 4 n-tiles (8) x 4 f32
    float acc[4][4][4];
#pragma unroll
    for (int i = 0; i < 4; i++)
#pragma unroll
        for (int j = 0; j < 4; j++)
#pragma unroll
            for (int c = 0; c < 4; c++) acc[i][j][c] = 0.0f;

    const uint32_t aWbase = sb + SM_A0  + (uint32_t)((wm * 64 + g) * ROWB + t * 4);
    const uint32_t bWbase = sb + SM_BF0 + (uint32_t)((wn * 32 + g) * ROWB + t * 4);

    // ---- main loop --------------------------------------------------------
#pragma unroll 1
    for (int s = 0; s < NST; s++) {
        const int slot = s % S;

        if (s + S - 1 < NST) { CP_WAIT(S - 2); } else { CP_WAIT(0); }

        // convert stage-s W ints -> fp16 buffer (parity s&1). Safe: previous
        // reader of this parity was compute(s-2), separated by barrier(s-1).
        {
            char* bi = smem + SM_BI0 + slot * BI_STAGE_B;
            char* bf = smem + SM_BF0 + (s & 1) * BF_BUF_B;
#pragma unroll
            for (int i = 0; i < 4; i++) {
                int4 v = *reinterpret_cast<const int4*>(bi + bIoff[i]);
                __half2 h0 = __halves2half2(__float2half_rn(__int2float_rn(v.x)),
                                            __float2half_rn(__int2float_rn(v.y)));
                __half2 h1 = __halves2half2(__float2half_rn(__int2float_rn(v.z)),
                                            __float2half_rn(__int2float_rn(v.w)));
                uint2 p;
                p.x = *reinterpret_cast<uint32_t*>(&h0);
                p.y = *reinterpret_cast<uint32_t*>(&h1);
                *reinterpret_cast<uint2*>(bf + bFoff[i]) = p;
            }
        }
        __syncthreads();

        // prefetch stage s+S-1 (its A/BI slot was freed by compute(s-1),
        // ordered by the barrier above)
        if (s + S - 1 < NST) {
            const int ps = s + S - 1;
            const int pb = ps % S;
            const uint32_t ab = sb + SM_A0  + pb * A_STAGE_B;
            const uint32_t bb = sb + SM_BI0 + pb * BI_STAGE_B;
            const int kb = ps * KC;
#pragma unroll
            for (int i = 0; i < 2; i++) CP_ASYNC16(ab + aSoff[i], aG[i] + kb);
#pragma unroll
            for (int i = 0; i < 4; i++) CP_ASYNC16(bb + bIoff[i], bG[i] + kb);
            CP_COMMIT();
        }

        // compute stage s: KC=32 -> two k16 steps
        const uint32_t aS = aWbase + slot * A_STAGE_B;
        const uint32_t bS = bWbase + (s & 1) * BF_BUF_B;
#pragma unroll
        for (int kk = 0; kk < 2; kk++) {
            const uint32_t ko = (uint32_t)(kk * 32);   // 16 halfs
            uint32_t a[4][4], b[4][2];
#pragma unroll
            for (int i = 0; i < 4; i++) {
                const uint32_t base = aS + (uint32_t)(i * 16 * ROWB) + ko;
                a[i][0] = lds_u32(base);                 // (g,      2t:2t+1)
                a[i][1] = lds_u32(base + 8 * ROWB);      // (g+8,    2t:2t+1)
                a[i][2] = lds_u32(base + 16);            // (g,      2t+8:+9)
                a[i][3] = lds_u32(base + 8 * ROWB + 16); // (g+8,    2t+8:+9)
            }
#pragma unroll
            for (int j = 0; j < 4; j++) {
                const uint32_t base = bS + (uint32_t)(j * 8 * ROWB) + ko;
                b[j][0] = lds_u32(base);                 // (k=2t:2t+1,  n=g)
                b[j][1] = lds_u32(base + 16);            // (k=2t+8:+9,  n=g)
            }
#pragma unroll
            for (int i = 0; i < 4; i++)
#pragma unroll
                for (int j = 0; j < 4; j++)
                    mma_f16(acc[i][j], a[i], b[j]);
        }
    }

    // ---- epilogue ---------------------------------------------------------
    const float* s_sc = (const float*)(smem + SM_SCALE);
    const float* s_bi = (const float*)(smem + SM_BIAS);
#pragma unroll
    for (int i = 0; i < 4; i++) {
        const int m = m0 + wm * 64 + i * 16 + g;
#pragma unroll
        for (int j = 0; j < 4; j++) {
            const int nl = wn * 32 + j * 8 + 2 * t;
            const float sc0 = s_sc[nl],     bi0 = s_bi[nl];
            const float sc1 = s_sc[nl + 1], bi1 = s_bi[nl + 1];
            float2 v0 = { acc[i][j][0] * sc0 + bi0, acc[i][j][1] * sc1 + bi1 };
            float2 v1 = { acc[i][j][2] * sc0 + bi0, acc[i][j][3] * sc1 + bi1 };
            *reinterpret_cast<float2*>(out + (size_t)m * OUT_F + n0 + nl) = v0;
            *reinterpret_cast<float2*>(out + (size_t)(m + 8) * OUT_F + n0 + nl) = v1;
        }
    }
}

// ---------------------------------------------------------------------------
extern "C" void kernel_launch(void* const* d_in, const int* in_sizes, int n_in,
                              void* d_out, int out_size) {
    const float* x     = (const float*)d_in[0];
    const int*   W     = (const int*)  d_in[1];
    const float* scale = (const float*)d_in[2];
    const float* bias  = (const float*)d_in[3];
    float*       out   = (float*)d_out;

    (void)in_sizes; (void)n_in; (void)out_size;

    cudaFuncSetAttribute(qlin_gemm_kernel,
                         cudaFuncAttributeMaxDynamicSharedMemorySize, SM_TOTAL);

    prep_x_kernel<<<(TOKENS * IN_F + 255) / 256, 256>>>(x);

    dim3 grid(OUT_F / N_TILE, TOKENS / M_TILE);   // (112, 2) -> 2 CTAs/SM
    qlin_gemm_kernel<<<grid, NTHREADS, SM_TOTAL>>>(W, scale, bias, out);
}

// round 8
// speedup vs baseline: 2.1594x; 1.1123x over previous
#include <cuda_runtime.h>
#include <cuda_fp16.h>
#include <cstdint>

// ---------------------------------------------------------------------------
// QuantizedLinear: y[t,o] = scale[o] * sum_k x[t,k]*qW[o,k] + bias[o]
// TOKENS=256, IN_F=4096, OUT_F=14336. qW int32 in [0,127) -> exact in fp16.
// fp16 mma.sync m16n8k16 (f32 accum), cp.async 3-stage pipeline, 2 CTAs/SM.
// R7 (resubmit): ldmatrix.x4 fragment loads + prmt/lop3/hsub2 magic convert.
// ---------------------------------------------------------------------------

#define TOKENS 256
#define IN_F   4096
#define OUT_F  14336

#define M_TILE 128
#define N_TILE 128
#define KC     32                 // K elems per stage
#define NST    (IN_F / KC)        // 128 stages
#define S      3                  // cp.async pipeline depth
#define NTHREADS 256

// fp16 tile rows: 32 halfs = 64B data + 16B pad = 80B. Bank stride 20 ->
// every ldmatrix 8-row x 16B phase covers all 32 banks once (conflict-free).
#define ROWB      80
#define A_STAGE_B (M_TILE * ROWB)     // 10240
#define BI_STAGE_B (N_TILE * 128)     // 16384 (int32 staging: 32*4B rows)
#define BF_BUF_B  (N_TILE * ROWB)     // 10240

#define SM_SCALE 0
#define SM_BIAS  512
#define SM_A0    1024
#define SM_BI0   (SM_A0 + S * A_STAGE_B)     // 31744
#define SM_BF0   (SM_BI0 + S * BI_STAGE_B)   // 80896
#define SM_TOTAL (SM_BF0 + 2 * BF_BUF_B)     // 101376 (x2 CTAs fits 227KB)

__device__ __half g_x_f16[TOKENS * IN_F];

// ---------------------------------------------------------------------------
__device__ __forceinline__ uint32_t smem_u32(const void* p) {
    uint32_t a;
    asm("{ .reg .u64 t; cvta.to.shared.u64 t, %1; cvt.u32.u64 %0, t; }"
        : "=r"(a) : "l"(p));
    return a;
}

#define CP_ASYNC16(dst, src) \
    asm volatile("cp.async.cg.shared.global [%0], [%1], 16;" :: "r"(dst), "l"(src))
#define CP_COMMIT() asm volatile("cp.async.commit_group;" ::: "memory")
#define CP_WAIT(n)  asm volatile("cp.async.wait_group %0;" :: "n"(n) : "memory")

#define LDMX4(r0, r1, r2, r3, addr) \
    asm volatile("ldmatrix.sync.aligned.m8n8.x4.shared.b16 {%0,%1,%2,%3}, [%4];" \
                 : "=r"(r0), "=r"(r1), "=r"(r2), "=r"(r3) : "r"(addr))

__device__ __forceinline__ void mma_f16(float* c, const uint32_t* a, const uint32_t* b) {
    asm volatile(
        "mma.sync.aligned.m16n8k16.row.col.f32.f16.f16.f32 "
        "{%0,%1,%2,%3}, {%4,%5,%6,%7}, {%8,%9}, {%0,%1,%2,%3};"
        : "+f"(c[0]), "+f"(c[1]), "+f"(c[2]), "+f"(c[3])
        : "r"(a[0]), "r"(a[1]), "r"(a[2]), "r"(a[3]), "r"(b[0]), "r"(b[1]));
}

// Exact int(0..126) pair -> fp16x2: gather low bytes, OR 0x6400 (=1024.0 bits,
// ULP=1 in [1024,2048)), subtract 1024. 3 ops per 2 elements.
__device__ __forceinline__ uint32_t int2_to_h2(uint32_t lo, uint32_t hi) {
    uint32_t p;
    asm("prmt.b32 %0, %1, %2, 0x5410;" : "=r"(p) : "r"(lo), "r"(hi));
    p = (p & 0x00FF00FFu) | 0x64006400u;          // one LOP3
    uint32_t r;
    asm("sub.rn.f16x2 %0, %1, %2;" : "=r"(r) : "r"(p), "r"(0x64006400u));
    return r;
}

// ---------------------------------------------------------------------------
__global__ void __launch_bounds__(256) prep_x_kernel(const float* __restrict__ x) {
    int i = blockIdx.x * blockDim.x + threadIdx.x;
    if (i < TOKENS * IN_F) g_x_f16[i] = __float2half_rn(x[i]);
}

// ---------------------------------------------------------------------------
__global__ void __launch_bounds__(NTHREADS, 2) qlin_gemm_kernel(
    const int*   __restrict__ W,
    const float* __restrict__ scale,
    const float* __restrict__ bias,
    float*       __restrict__ out)
{
    extern __shared__ char smem[];
    const uint32_t sb = smem_u32(smem);
    const int tid = threadIdx.x;
    const int wid = tid >> 5;
    const int lid = tid & 31;
    const int g   = lid >> 2;
    const int t   = lid & 3;
    const int wm  = wid & 1;     // 2 M warp-rows (64 tokens)
    const int wn  = wid >> 1;    // 4 N warp-cols (32 feats)
    const int n0  = blockIdx.x * N_TILE;
    const int m0  = blockIdx.y * M_TILE;

    if (tid < N_TILE) {
        ((float*)(smem + SM_SCALE))[tid] = scale[n0 + tid];
        ((float*)(smem + SM_BIAS))[tid]  = bias[n0 + tid];
    }

    // ---- cp.async chunk mapping ------------------------------------------
    uint32_t aSoff[2]; const __half* aG[2];
#pragma unroll
    for (int i = 0; i < 2; i++) {
        int c = tid + i * NTHREADS;         // 0..511
        int row = c >> 2, ca = c & 3;
        aSoff[i] = (uint32_t)(row * ROWB + ca * 16);
        aG[i]    = g_x_f16 + (size_t)(m0 + row) * IN_F + ca * 8;
    }
    uint32_t bIoff[4], bFoff[4]; const int* bG[4];
#pragma unroll
    for (int i = 0; i < 4; i++) {
        int c = tid + i * NTHREADS;         // 0..1023
        int row = c >> 3, cb = c & 7;
        bIoff[i] = (uint32_t)(row * 128 + cb * 16);
        bFoff[i] = (uint32_t)(row * ROWB + cb * 8);
        bG[i]    = W + (size_t)(n0 + row) * IN_F + cb * 4;
    }

    // ---- prologue ---------------------------------------------------------
#pragma unroll
    for (int s = 0; s < S - 1; s++) {
        const uint32_t ab = sb + SM_A0  + s * A_STAGE_B;
        const uint32_t bb = sb + SM_BI0 + s * BI_STAGE_B;
        const int kb = s * KC;
#pragma unroll
        for (int i = 0; i < 2; i++) CP_ASYNC16(ab + aSoff[i], aG[i] + kb);
#pragma unroll
        for (int i = 0; i < 4; i++) CP_ASYNC16(bb + bIoff[i], bG[i] + kb);
        CP_COMMIT();
    }

    float acc[4][4][4];
#pragma unroll
    for (int i = 0; i < 4; i++)
#pragma unroll
        for (int j = 0; j < 4; j++)
#pragma unroll
            for (int c = 0; c < 4; c++) acc[i][j][c] = 0.0f;

    // ---- per-thread ldmatrix bases ---------------------------------------
    // A x4 tile (16 rows x 16 k): lane groups 0-7/8-15/16-23/24-31 address
    // (r+0,k0)/(r+8,k0)/(r+0,k8)/(r+8,k8) -> {a0,a1,a2,a3} directly.
    const uint32_t aLM = sb + SM_A0 +
        (uint32_t)((wm * 64 + (lid & 7) + 8 * ((lid >> 3) & 1)) * ROWB
                   + (lid >> 4) * 16);
    // B x4 tile (16 n-rows x 16 k): groups address (n+0,k0)/(n+0,k8)/
    // (n+8,k0)/(n+8,k8) -> {b[2j][0],b[2j][1],b[2j+1][0],b[2j+1][1]}.
    const uint32_t bLM = sb + SM_BF0 +
        (uint32_t)((wn * 32 + (lid & 7) + 8 * (lid >> 4)) * ROWB
                   + ((lid >> 3) & 1) * 16);

    // ---- main loop --------------------------------------------------------
#pragma unroll 1
    for (int s = 0; s < NST; s++) {
        const int slot = s % S;

        if (s + S - 1 < NST) { CP_WAIT(S - 2); } else { CP_WAIT(0); }

        // convert stage-s W ints -> fp16 buffer (parity s&1). Safe: previous
        // reader of this parity was compute(s-2), separated by barrier(s-1).
        {
            char* bi = smem + SM_BI0 + slot * BI_STAGE_B;
            char* bf = smem + SM_BF0 + (s & 1) * BF_BUF_B;
#pragma unroll
            for (int i = 0; i < 4; i++) {
                int4 v = *reinterpret_cast<const int4*>(bi + bIoff[i]);
                uint2 p;
                p.x = int2_to_h2((uint32_t)v.x, (uint32_t)v.y);
                p.y = int2_to_h2((uint32_t)v.z, (uint32_t)v.w);
                *reinterpret_cast<uint2*>(bf + bFoff[i]) = p;
            }
        }
        __syncthreads();

        // prefetch stage s+S-1 (slot freed by compute(s-1), ordered above)
        if (s + S - 1 < NST) {
            const int ps = s + S - 1;
            const int pb = ps % S;
            const uint32_t ab = sb + SM_A0  + pb * A_STAGE_B;
            const uint32_t bb = sb + SM_BI0 + pb * BI_STAGE_B;
            const int kb = ps * KC;
#pragma unroll
            for (int i = 0; i < 2; i++) CP_ASYNC16(ab + aSoff[i], aG[i] + kb);
#pragma unroll
            for (int i = 0; i < 4; i++) CP_ASYNC16(bb + bIoff[i], bG[i] + kb);
            CP_COMMIT();
        }

        // compute stage s: two k16 steps, fragments via ldmatrix.x4
        const uint32_t aS = aLM + slot * A_STAGE_B;
        const uint32_t bS = bLM + (s & 1) * BF_BUF_B;
#pragma unroll
        for (int kk = 0; kk < 2; kk++) {
            const uint32_t ko = (uint32_t)(kk * 32);   // 16 halfs
            uint32_t a[4][4], b[4][2];
#pragma unroll
            for (int i = 0; i < 4; i++)
                LDMX4(a[i][0], a[i][1], a[i][2], a[i][3],
                      aS + (uint32_t)(i * 16 * ROWB) + ko);
#pragma unroll
            for (int jp = 0; jp < 2; jp++)
                LDMX4(b[2 * jp][0], b[2 * jp][1], b[2 * jp + 1][0], b[2 * jp + 1][1],
                      bS + (uint32_t)(jp * 16 * ROWB) + ko);
#pragma unroll
            for (int i = 0; i < 4; i++)
#pragma unroll
                for (int j = 0; j < 4; j++)
                    mma_f16(acc[i][j], a[i], b[j]);
        }
    }

    // ---- epilogue ---------------------------------------------------------
    const float* s_sc = (const float*)(smem + SM_SCALE);
    const float* s_bi = (const float*)(smem + SM_BIAS);
#pragma unroll
    for (int i = 0; i < 4; i++) {
        const int m = m0 + wm * 64 + i * 16 + g;
#pragma unroll
        for (int j = 0; j < 4; j++) {
            const int nl = wn * 32 + j * 8 + 2 * t;
            const float sc0 = s_sc[nl],     bi0 = s_bi[nl];
            const float sc1 = s_sc[nl + 1], bi1 = s_bi[nl + 1];
            float2 v0 = { acc[i][j][0] * sc0 + bi0, acc[i][j][1] * sc1 + bi1 };
            float2 v1 = { acc[i][j][2] * sc0 + bi0, acc[i][j][3] * sc1 + bi1 };
            *reinterpret_cast<float2*>(out + (size_t)m * OUT_F + n0 + nl) = v0;
            *reinterpret_cast<float2*>(out + (size_t)(m + 8) * OUT_F + n0 + nl) = v1;
        }
    }
}

// ---------------------------------------------------------------------------
extern "C" void kernel_launch(void* const* d_in, const int* in_sizes, int n_in,
                              void* d_out, int out_size) {
    const float* x     = (const float*)d_in[0];
    const int*   W     = (const int*)  d_in[1];
    const float* scale = (const float*)d_in[2];
    const float* bias  = (const float*)d_in[3];
    float*       out   = (float*)d_out;

    (void)in_sizes; (void)n_in; (void)out_size;

    cudaFuncSetAttribute(qlin_gemm_kernel,
                         cudaFuncAttributeMaxDynamicSharedMemorySize, SM_TOTAL);

    prep_x_kernel<<<(TOKENS * IN_F + 255) / 256, 256>>>(x);

    dim3 grid(OUT_F / N_TILE, TOKENS / M_TILE);   // (112, 2) -> 2 CTAs/SM
    qlin_gemm_kernel<<<grid, NTHREADS, SM_TOTAL>>>(W, scale, bias, out);
}